// round 8
// baseline (speedup 1.0000x reference)
#include <cuda_runtime.h>
#include <cstdint>

#define NN 4096
#define EE 8192
#define FDIM 64
#define BN_EPS 1e-5f
#define TRIP_CAP 131072
#define TOTROWS (NN + EE + NN)
#define NBLK 592            // 148 SMs x 4 CTAs (48KB smem each)

// ---------------- device scratch ----------------
__device__ float g_pd_y[NN * FDIM];
__device__ float g_x[NN * FDIM];
__device__ float g_lg_y[EE * FDIM];
__device__ float g_pm_x[EE * FDIM];
__device__ float g_stats[256];
__device__ int   g_cnt;
__device__ unsigned g_row_ctr;
__device__ int   g_trip_n[TRIP_CAP];
__device__ int   g_trip_e[TRIP_CAP];
__device__ float g_trip_v[TRIP_CAP];

// ---------------- init ----------------
__global__ __launch_bounds__(256) void k_init() {
    int idx = blockIdx.x * 256 + threadIdx.x;              // 512*256 = 131072
    reinterpret_cast<float4*>(g_pm_x)[idx] = make_float4(0.f, 0.f, 0.f, 0.f);
    if (idx < 256) g_stats[idx] = 0.f;
    if (idx == 0) { g_cnt = 0; g_row_ctr = 0u; }
}

// ---------------- helpers ----------------
__device__ __forceinline__ unsigned nz4(float4 v) {
    return __float_as_uint(v.x) | __float_as_uint(v.y) |
           __float_as_uint(v.z) | __float_as_uint(v.w);
}

__device__ __forceinline__ void gath_chunk(float4 v, unsigned ored, int colbase, int lane,
                                           const float* __restrict__ B,
                                           float& acc0, float& acc1) {
    unsigned mask = __ballot_sync(0xffffffffu, ored != 0u);
    while (mask) {
        int src = __ffs(mask) - 1;
        mask &= mask - 1;
        float b0 = __shfl_sync(0xffffffffu, v.x, src);
        float b1 = __shfl_sync(0xffffffffu, v.y, src);
        float b2 = __shfl_sync(0xffffffffu, v.z, src);
        float b3 = __shfl_sync(0xffffffffu, v.w, src);
        const float* bp = B + (size_t)(colbase + (src << 2)) * FDIM + lane;
        if (b0 != 0.f) { acc0 = fmaf(b0, bp[0],   acc0); acc1 = fmaf(b0, bp[32],  acc1); }
        if (b1 != 0.f) { acc0 = fmaf(b1, bp[64],  acc0); acc1 = fmaf(b1, bp[96],  acc1); }
        if (b2 != 0.f) { acc0 = fmaf(b2, bp[128], acc0); acc1 = fmaf(b2, bp[160], acc1); }
        if (b3 != 0.f) { acc0 = fmaf(b3, bp[192], acc0); acc1 = fmaf(b3, bp[224], acc1); }
    }
}

__device__ __forceinline__ void pm_emit(float4 v, int col0, int n) {
    int k = (v.x != 0.f) + (v.y != 0.f) + (v.z != 0.f) + (v.w != 0.f);
    if (!k) return;
    int pos = atomicAdd(&g_cnt, k);
    float vals[4] = {v.x, v.y, v.z, v.w};
    #pragma unroll
    for (int j = 0; j < 4; ++j) {
        if (vals[j] != 0.f && pos < TRIP_CAP) {
            g_trip_n[pos] = n;
            g_trip_e[pos] = col0 + j;
            g_trip_v[pos] = vals[j];
            ++pos;
        }
    }
}

__device__ __forceinline__ void cp16(uint32_t saddr, const float4* gaddr) {
    asm volatile("cp.async.cg.shared.global [%0], [%1], 16;"
                 :: "r"(saddr), "l"(gaddr) : "memory");
}
#define CP_COMMIT() asm volatile("cp.async.commit_group;" ::: "memory")
#define CP_WAIT(n)  asm volatile("cp.async.wait_group %0;" :: "n"(n) : "memory")

// ---------------- cp.async-pipelined persistent mega-scan ----------------
// Per-warp private 3-stage x 2KB smem ring; no inter-warp sync.
// rows: pd [0,4096), lg [4096,12288), pm [12288,16384)
__global__ void __launch_bounds__(256, 4) k_megascan(const float* __restrict__ pd,
                                                     const float* __restrict__ lg,
                                                     const float* __restrict__ pm,
                                                     const float* __restrict__ y) {
    __shared__ __align__(16) float4 s_buf[8][3][128];   // 48KB
    int lane = threadIdx.x & 31;
    int w = threadIdx.x >> 5;

    uint32_t sb[3];
    #pragma unroll
    for (int st = 0; st < 3; ++st)
        sb[st] = (uint32_t)__cvta_generic_to_shared(&s_buf[w][st][lane]);

    while (true) {
        unsigned rowid;
        if (lane == 0) rowid = atomicAdd(&g_row_ctr, 1u);
        rowid = __shfl_sync(0xffffffffu, rowid, 0);
        if (rowid >= TOTROWS) return;

        const float4* arow;
        int mode, row;
        if (rowid < NN)            { mode = 0; row = (int)rowid;           arow = reinterpret_cast<const float4*>(pd + (size_t)row * EE); }
        else if (rowid < NN + EE)  { mode = 1; row = (int)rowid - NN;      arow = reinterpret_cast<const float4*>(lg + (size_t)row * EE); }
        else                       { mode = 2; row = (int)rowid - NN - EE; arow = reinterpret_cast<const float4*>(pm + (size_t)row * EE); }

        // prologue: stages 0..2  (stage g covers float4 [g*128, (g+1)*128))
        #pragma unroll
        for (int g = 0; g < 3; ++g) {
            const float4* src = arow + (g << 7) + lane;
            #pragma unroll
            for (int j = 0; j < 4; ++j)
                cp16(sb[g] + j * 32 * 16, src + (j << 5));
            CP_COMMIT();
        }

        float acc0 = 0.f, acc1 = 0.f;

        #pragma unroll 1
        for (int g = 0; g < 16; ++g) {                  // 16 stages of 512 floats
            CP_WAIT(2);                                  // stage g landed
            int st = g - (g / 3) * 3;
            const float4* stage = &s_buf[w][st][lane];
            float4 v0 = stage[0];
            float4 v1 = stage[32];
            float4 v2 = stage[64];
            float4 v3 = stage[96];

            // refill this stage buffer for stage g+3
            if (g < 13) {
                const float4* src = arow + ((g + 3) << 7) + lane;
                #pragma unroll
                for (int j = 0; j < 4; ++j)
                    cp16(sb[st] + j * 32 * 16, src + (j << 5));
            }
            CP_COMMIT();   // commit (possibly empty) group to keep count in step

            unsigned o0 = nz4(v0), o1 = nz4(v1), o2 = nz4(v2), o3 = nz4(v3);
            if (__ballot_sync(0xffffffffu, (o0 | o1 | o2 | o3) != 0u)) {
                int cb = g << 9;
                if (mode < 2) {
                    gath_chunk(v0, o0, cb,       lane, y, acc0, acc1);
                    gath_chunk(v1, o1, cb + 128, lane, y, acc0, acc1);
                    gath_chunk(v2, o2, cb + 256, lane, y, acc0, acc1);
                    gath_chunk(v3, o3, cb + 384, lane, y, acc0, acc1);
                } else {
                    int lb = cb + (lane << 2);
                    if (o0) pm_emit(v0, lb,       row);
                    if (o1) pm_emit(v1, lb + 128, row);
                    if (o2) pm_emit(v2, lb + 256, row);
                    if (o3) pm_emit(v3, lb + 384, row);
                }
            }
        }

        if (mode < 2) {
            float* out = (mode == 0 ? g_pd_y : g_lg_y) + (size_t)row * FDIM;
            out[lane]      = acc0;
            out[lane + 32] = acc1;
        }
        CP_WAIT(0);   // drain before next row reuses buffers
    }
}

// ---------------- x linear + concat/relu + BN-x stats ----------------
__global__ __launch_bounds__(256) void k_x_linear(const float* __restrict__ tw,
                                                  const float* __restrict__ tb,
                                                  const float* __restrict__ trw,
                                                  const float* __restrict__ trb) {
    __shared__ float s_in[16 * 64];
    __shared__ float red[256], red2[256];
    int t = threadIdx.x;
    int rowbase = blockIdx.x * 16;
    reinterpret_cast<float4*>(s_in)[t] =
        reinterpret_cast<const float4*>(g_pd_y + (size_t)rowbase * 64)[t];
    __syncthreads();
    int c = t & 63, slot = t >> 6;
    const float* w; float bias; bool dorelu;
    if (c < 32) { w = tw + c * 64;         bias = tb[c];        dorelu = false; }
    else        { w = trw + (c - 32) * 64; bias = trb[c - 32];  dorelu = true;  }
    float acc[4] = {bias, bias, bias, bias};
    #pragma unroll
    for (int f = 0; f < 64; f += 4) {
        float4 wv = *reinterpret_cast<const float4*>(w + f);
        #pragma unroll
        for (int j = 0; j < 4; ++j) {
            float4 pv = *reinterpret_cast<const float4*>(&s_in[(slot + 4 * j) * 64 + f]);
            acc[j] = fmaf(wv.x, pv.x, fmaf(wv.y, pv.y, fmaf(wv.z, pv.z, fmaf(wv.w, pv.w, acc[j]))));
        }
    }
    float s = 0.f, sq = 0.f;
    #pragma unroll
    for (int j = 0; j < 4; ++j) {
        float v = acc[j];
        if (dorelu) v = fmaxf(v, 0.f);
        g_x[(size_t)(rowbase + slot + 4 * j) * 64 + c] = v;
        s += v; sq += v * v;
    }
    red[t] = s; red2[t] = sq;
    __syncthreads();
    if (slot == 0) {
        atomicAdd(&g_stats[c],      red[c] + red[64 + c] + red[128 + c] + red[192 + c]);
        atomicAdd(&g_stats[64 + c], red2[c] + red2[64 + c] + red2[128 + c] + red2[192 + c]);
    }
}

// ---------------- pm triplet apply, fused x-BN, batched per warp ----------------
__global__ __launch_bounds__(256) void k_pm_apply(const float* __restrict__ bxw,
                                                  const float* __restrict__ bxb) {
    int lane = threadIdx.x & 31;
    int warp = (blockIdx.x * 256 + threadIdx.x) >> 5;   // 4096 warps

    int cnt = g_cnt;
    if (cnt > TRIP_CAP) cnt = TRIP_CAP;
    int K = (cnt + 4095) >> 12;
    int base = warp * K;
    int m = cnt - base; if (m < 0) m = 0; if (m > K) m = K;
    if (m == 0) return;

    const float invn = 1.f / NN;
    float m0 = g_stats[lane] * invn;
    float m1 = g_stats[lane + 32] * invn;
    float v0 = g_stats[64 + lane] * invn - m0 * m0;
    float v1 = g_stats[64 + lane + 32] * invn - m1 * m1;
    float sc0 = bxw[lane] * rsqrtf(v0 + BN_EPS);
    float sc1 = bxw[lane + 32] * rsqrtf(v1 + BN_EPS);
    float sh0 = bxb[lane] - m0 * sc0;
    float sh1 = bxb[lane + 32] - m1 * sc1;

    for (int j0 = 0; j0 < m; j0 += 8) {
        int mm = m - j0; if (mm > 8) mm = 8;
        int n_[8], e_[8]; float v_[8], x0_[8], x1_[8];
        #pragma unroll
        for (int j = 0; j < 8; ++j) if (j < mm) {
            n_[j] = g_trip_n[base + j0 + j];
            e_[j] = g_trip_e[base + j0 + j];
            v_[j] = g_trip_v[base + j0 + j];
        }
        #pragma unroll
        for (int j = 0; j < 8; ++j) if (j < mm) {
            x0_[j] = g_x[(size_t)n_[j] * 64 + lane];
            x1_[j] = g_x[(size_t)n_[j] * 64 + lane + 32];
        }
        #pragma unroll
        for (int j = 0; j < 8; ++j) if (j < mm) {
            float a0 = v_[j] * fmaf(x0_[j], sc0, sh0);
            float a1 = v_[j] * fmaf(x1_[j], sc1, sh1);
            atomicAdd(&g_pm_x[(size_t)e_[j] * 64 + lane],      a0);
            atomicAdd(&g_pm_x[(size_t)e_[j] * 64 + lane + 32], a1);
        }
    }
}

// ---------------- y combine + concat/relu + BN-y stats -> out ----------------
__global__ __launch_bounds__(256) void k_y_linear(const float* __restrict__ gaw,
                                                  const float* __restrict__ gab,
                                                  const float* __restrict__ gxw,
                                                  const float* __restrict__ gxb,
                                                  const float* __restrict__ garw,
                                                  const float* __restrict__ garb,
                                                  const float* __restrict__ gxrw,
                                                  const float* __restrict__ gxrb,
                                                  float* __restrict__ out) {
    __shared__ float s_lg[16 * 64];
    __shared__ float s_pm[16 * 64];
    __shared__ float red[256], red2[256];
    int t = threadIdx.x;
    int rowbase = blockIdx.x * 16;
    reinterpret_cast<float4*>(s_lg)[t] =
        reinterpret_cast<const float4*>(g_lg_y + (size_t)rowbase * 64)[t];
    reinterpret_cast<float4*>(s_pm)[t] =
        reinterpret_cast<const float4*>(g_pm_x + (size_t)rowbase * 64)[t];
    __syncthreads();
    int c = t & 63, slot = t >> 6;
    const float *wa, *wx; float bias; bool dorelu;
    if (c < 32) { wa = gaw + c * 64;   wx = gxw + c * 64;
                  bias = gab[c] + gxb[c];            dorelu = false; }
    else        { int cr = c - 32;
                  wa = garw + cr * 64; wx = gxrw + cr * 64;
                  bias = garb[cr] + gxrb[cr];        dorelu = true;  }
    float acc[4] = {bias, bias, bias, bias};
    #pragma unroll
    for (int f = 0; f < 64; f += 4) {
        float4 wav = *reinterpret_cast<const float4*>(wa + f);
        float4 wxv = *reinterpret_cast<const float4*>(wx + f);
        #pragma unroll
        for (int j = 0; j < 4; ++j) {
            float4 pa = *reinterpret_cast<const float4*>(&s_lg[(slot + 4 * j) * 64 + f]);
            float4 px = *reinterpret_cast<const float4*>(&s_pm[(slot + 4 * j) * 64 + f]);
            float a = acc[j];
            a = fmaf(wav.x, pa.x, fmaf(wav.y, pa.y, fmaf(wav.z, pa.z, fmaf(wav.w, pa.w, a))));
            a = fmaf(wxv.x, px.x, fmaf(wxv.y, px.y, fmaf(wxv.z, px.z, fmaf(wxv.w, px.w, a))));
            acc[j] = a;
        }
    }
    float s = 0.f, sq = 0.f;
    #pragma unroll
    for (int j = 0; j < 4; ++j) {
        float v = acc[j];
        if (dorelu) v = fmaxf(v, 0.f);
        out[(size_t)(rowbase + slot + 4 * j) * 64 + c] = v;
        s += v; sq += v * v;
    }
    red[t] = s; red2[t] = sq;
    __syncthreads();
    if (slot == 0) {
        atomicAdd(&g_stats[128 + c], red[c] + red[64 + c] + red[128 + c] + red[192 + c]);
        atomicAdd(&g_stats[192 + c], red2[c] + red2[64 + c] + red2[128 + c] + red2[192 + c]);
    }
}

// ---------------- final BN on y (vectorized, in place) ----------------
__global__ __launch_bounds__(256) void k_bn_y(float4* __restrict__ buf,
                                              const float* __restrict__ w,
                                              const float* __restrict__ b) {
    int idx = blockIdx.x * 256 + threadIdx.x;
    const float inve = 1.f / EE;
    int c0 = (idx & 15) << 2;
    float4 v = buf[idx];
    float* vp = reinterpret_cast<float*>(&v);
    #pragma unroll
    for (int j = 0; j < 4; ++j) {
        int c = c0 + j;
        float m = g_stats[128 + c] * inve;
        float var = g_stats[192 + c] * inve - m * m;
        float sc = w[c] * rsqrtf(var + BN_EPS);
        vp[j] = (vp[j] - m) * sc + b[c];
    }
    buf[idx] = v;
}

// ---------------- launch ----------------
extern "C" void kernel_launch(void* const* d_in, const int* in_sizes, int n_in,
                              void* d_out, int out_size) {
    const float* y    = (const float*)d_in[0];
    const float* lg   = (const float*)d_in[3];
    const float* pm   = (const float*)d_in[4];
    const float* pd   = (const float*)d_in[5];
    const float* tw   = (const float*)d_in[6];
    const float* tb   = (const float*)d_in[7];
    const float* trw  = (const float*)d_in[8];
    const float* trb  = (const float*)d_in[9];
    const float* gaw  = (const float*)d_in[10];
    const float* gab  = (const float*)d_in[11];
    const float* gxw  = (const float*)d_in[12];
    const float* gxb  = (const float*)d_in[13];
    const float* garw = (const float*)d_in[14];
    const float* garb = (const float*)d_in[15];
    const float* gxrw = (const float*)d_in[16];
    const float* gxrb = (const float*)d_in[17];
    const float* bxw  = (const float*)d_in[18];
    const float* bxb  = (const float*)d_in[19];
    const float* byw  = (const float*)d_in[20];
    const float* byb  = (const float*)d_in[21];
    float* out = (float*)d_out;

    k_init<<<512, 256>>>();
    k_megascan<<<NBLK, 256>>>(pd, lg, pm, y);
    k_x_linear<<<NN / 16, 256>>>(tw, tb, trw, trb);
    k_pm_apply<<<512, 256>>>(bxw, bxb);
    k_y_linear<<<EE / 16, 256>>>(gaw, gab, gxw, gxb, garw, garb, gxrw, gxrb, out);
    k_bn_y<<<512, 256>>>((float4*)out, byw, byb);
}

// round 9
// speedup vs baseline: 1.0027x; 1.0027x over previous
#include <cuda_runtime.h>
#include <cstdint>

#define NN 4096
#define EE 8192
#define FDIM 64
#define BN_EPS 1e-5f
#define TRIP_CAP 131072
#define NBLK 740

// ---------------- device scratch ----------------
__device__ float g_pd_y[NN * FDIM];
__device__ float g_x[NN * FDIM];
__device__ float g_lg_y[EE * FDIM];
__device__ float g_pm_x[EE * FDIM];
__device__ float g_stats[256];
__device__ int   g_cnt;
__device__ unsigned g_ctrA, g_ctrB;
__device__ int   g_trip_n[TRIP_CAP];
__device__ int   g_trip_e[TRIP_CAP];
__device__ float g_trip_v[TRIP_CAP];

// ---------------- init ----------------
__global__ __launch_bounds__(256) void k_init() {
    int idx = blockIdx.x * 256 + threadIdx.x;              // 512*256 = 131072
    reinterpret_cast<float4*>(g_pm_x)[idx] = make_float4(0.f, 0.f, 0.f, 0.f);
    if (idx < 256) g_stats[idx] = 0.f;
    if (idx == 0) { g_cnt = 0; g_ctrA = 0u; g_ctrB = 0u; }
}

// ---------------- helpers ----------------
__device__ __forceinline__ unsigned nz4(float4 v) {
    return __float_as_uint(v.x) | __float_as_uint(v.y) |
           __float_as_uint(v.z) | __float_as_uint(v.w);
}

__device__ __forceinline__ void gath_chunk(float4 v, unsigned ored, int colbase, int lane,
                                           const float* __restrict__ B,
                                           float& acc0, float& acc1) {
    unsigned mask = __ballot_sync(0xffffffffu, ored != 0u);
    while (mask) {
        int src = __ffs(mask) - 1;
        mask &= mask - 1;
        float b0 = __shfl_sync(0xffffffffu, v.x, src);
        float b1 = __shfl_sync(0xffffffffu, v.y, src);
        float b2 = __shfl_sync(0xffffffffu, v.z, src);
        float b3 = __shfl_sync(0xffffffffu, v.w, src);
        const float* bp = B + (size_t)(colbase + (src << 2)) * FDIM + lane;
        if (b0 != 0.f) { acc0 = fmaf(b0, bp[0],   acc0); acc1 = fmaf(b0, bp[32],  acc1); }
        if (b1 != 0.f) { acc0 = fmaf(b1, bp[64],  acc0); acc1 = fmaf(b1, bp[96],  acc1); }
        if (b2 != 0.f) { acc0 = fmaf(b2, bp[128], acc0); acc1 = fmaf(b2, bp[160], acc1); }
        if (b3 != 0.f) { acc0 = fmaf(b3, bp[192], acc0); acc1 = fmaf(b3, bp[224], acc1); }
    }
}

__device__ __forceinline__ void pm_emit(float4 v, int col0, int n) {
    int k = (v.x != 0.f) + (v.y != 0.f) + (v.z != 0.f) + (v.w != 0.f);
    if (!k) return;
    int pos = atomicAdd(&g_cnt, k);
    float vals[4] = {v.x, v.y, v.z, v.w};
    #pragma unroll
    for (int j = 0; j < 4; ++j) {
        if (vals[j] != 0.f && pos < TRIP_CAP) {
            g_trip_n[pos] = n;
            g_trip_e[pos] = col0 + j;
            g_trip_v[pos] = vals[j];
            ++pos;
        }
    }
}

// ---------------- persistent scan A: pd gather rows [0,4096) + pm emit rows [4096,8192) ----------------
__global__ void __launch_bounds__(256, 5) k_scan_a(const float* __restrict__ pd,
                                                   const float* __restrict__ pm,
                                                   const float* __restrict__ y) {
    int lane = threadIdx.x & 31;
    while (true) {
        unsigned rowid;
        if (lane == 0) rowid = atomicAdd(&g_ctrA, 1u);
        rowid = __shfl_sync(0xffffffffu, rowid, 0);
        if (rowid >= 2u * NN) return;

        bool ispm = rowid >= NN;
        int row = ispm ? (int)rowid - NN : (int)rowid;
        const float4* arow = reinterpret_cast<const float4*>(
            (ispm ? pm : pd) + (size_t)row * EE);

        if (!ispm) {
            float acc0 = 0.f, acc1 = 0.f;
            #pragma unroll 1
            for (int g = 0; g < EE / 512; ++g) {
                int fb = (g << 7) + lane;
                float4 v0 = __ldcs(arow + fb);
                float4 v1 = __ldcs(arow + fb + 32);
                float4 v2 = __ldcs(arow + fb + 64);
                float4 v3 = __ldcs(arow + fb + 96);
                unsigned o0 = nz4(v0), o1 = nz4(v1), o2 = nz4(v2), o3 = nz4(v3);
                if (__ballot_sync(0xffffffffu, (o0 | o1 | o2 | o3) != 0u)) {
                    int cb = g << 9;
                    gath_chunk(v0, o0, cb,       lane, y, acc0, acc1);
                    gath_chunk(v1, o1, cb + 128, lane, y, acc0, acc1);
                    gath_chunk(v2, o2, cb + 256, lane, y, acc0, acc1);
                    gath_chunk(v3, o3, cb + 384, lane, y, acc0, acc1);
                }
            }
            g_pd_y[(size_t)row * FDIM + lane]      = acc0;
            g_pd_y[(size_t)row * FDIM + lane + 32] = acc1;
        } else {
            #pragma unroll 1
            for (int g = 0; g < EE / 512; ++g) {
                int fb = (g << 7) + lane;
                float4 v0 = __ldcs(arow + fb);
                float4 v1 = __ldcs(arow + fb + 32);
                float4 v2 = __ldcs(arow + fb + 64);
                float4 v3 = __ldcs(arow + fb + 96);
                unsigned o0 = nz4(v0), o1 = nz4(v1), o2 = nz4(v2), o3 = nz4(v3);
                if (__ballot_sync(0xffffffffu, (o0 | o1 | o2 | o3) != 0u)) {
                    int cb = (g << 9) + (lane << 2);
                    if (o0) pm_emit(v0, cb,       row);
                    if (o1) pm_emit(v1, cb + 128, row);
                    if (o2) pm_emit(v2, cb + 256, row);
                    if (o3) pm_emit(v3, cb + 384, row);
                }
            }
        }
    }
}

// ---------------- persistent scan B: lg gather rows [0,8192) ----------------
__global__ void __launch_bounds__(256, 5) k_scan_b(const float* __restrict__ lg,
                                                   const float* __restrict__ y) {
    int lane = threadIdx.x & 31;
    while (true) {
        unsigned rowid;
        if (lane == 0) rowid = atomicAdd(&g_ctrB, 1u);
        rowid = __shfl_sync(0xffffffffu, rowid, 0);
        if (rowid >= (unsigned)EE) return;
        int row = (int)rowid;
        const float4* arow = reinterpret_cast<const float4*>(lg + (size_t)row * EE);

        float acc0 = 0.f, acc1 = 0.f;
        #pragma unroll 1
        for (int g = 0; g < EE / 512; ++g) {
            int fb = (g << 7) + lane;
            float4 v0 = __ldcs(arow + fb);
            float4 v1 = __ldcs(arow + fb + 32);
            float4 v2 = __ldcs(arow + fb + 64);
            float4 v3 = __ldcs(arow + fb + 96);
            unsigned o0 = nz4(v0), o1 = nz4(v1), o2 = nz4(v2), o3 = nz4(v3);
            if (__ballot_sync(0xffffffffu, (o0 | o1 | o2 | o3) != 0u)) {
                int cb = g << 9;
                gath_chunk(v0, o0, cb,       lane, y, acc0, acc1);
                gath_chunk(v1, o1, cb + 128, lane, y, acc0, acc1);
                gath_chunk(v2, o2, cb + 256, lane, y, acc0, acc1);
                gath_chunk(v3, o3, cb + 384, lane, y, acc0, acc1);
            }
        }
        g_lg_y[(size_t)row * FDIM + lane]      = acc0;
        g_lg_y[(size_t)row * FDIM + lane + 32] = acc1;
    }
}

// ---------------- x linear + concat/relu + BN-x stats ----------------
__global__ __launch_bounds__(256) void k_x_linear(const float* __restrict__ tw,
                                                  const float* __restrict__ tb,
                                                  const float* __restrict__ trw,
                                                  const float* __restrict__ trb) {
    __shared__ float s_in[16 * 64];
    __shared__ float red[256], red2[256];
    int t = threadIdx.x;
    int rowbase = blockIdx.x * 16;
    reinterpret_cast<float4*>(s_in)[t] =
        reinterpret_cast<const float4*>(g_pd_y + (size_t)rowbase * 64)[t];
    __syncthreads();
    int c = t & 63, slot = t >> 6;
    const float* w; float bias; bool dorelu;
    if (c < 32) { w = tw + c * 64;         bias = tb[c];        dorelu = false; }
    else        { w = trw + (c - 32) * 64; bias = trb[c - 32];  dorelu = true;  }
    float acc[4] = {bias, bias, bias, bias};
    #pragma unroll
    for (int f = 0; f < 64; f += 4) {
        float4 wv = *reinterpret_cast<const float4*>(w + f);
        #pragma unroll
        for (int j = 0; j < 4; ++j) {
            float4 pv = *reinterpret_cast<const float4*>(&s_in[(slot + 4 * j) * 64 + f]);
            acc[j] = fmaf(wv.x, pv.x, fmaf(wv.y, pv.y, fmaf(wv.z, pv.z, fmaf(wv.w, pv.w, acc[j]))));
        }
    }
    float s = 0.f, sq = 0.f;
    #pragma unroll
    for (int j = 0; j < 4; ++j) {
        float v = acc[j];
        if (dorelu) v = fmaxf(v, 0.f);
        g_x[(size_t)(rowbase + slot + 4 * j) * 64 + c] = v;
        s += v; sq += v * v;
    }
    red[t] = s; red2[t] = sq;
    __syncthreads();
    if (slot == 0) {
        atomicAdd(&g_stats[c],      red[c] + red[64 + c] + red[128 + c] + red[192 + c]);
        atomicAdd(&g_stats[64 + c], red2[c] + red2[64 + c] + red2[128 + c] + red2[192 + c]);
    }
}

// ---------------- pm triplet apply, fused x-BN, batched per warp ----------------
__global__ __launch_bounds__(256) void k_pm_apply(const float* __restrict__ bxw,
                                                  const float* __restrict__ bxb) {
    int lane = threadIdx.x & 31;
    int warp = (blockIdx.x * 256 + threadIdx.x) >> 5;   // 4096 warps

    int cnt = g_cnt;
    if (cnt > TRIP_CAP) cnt = TRIP_CAP;
    int K = (cnt + 4095) >> 12;
    int base = warp * K;
    int m = cnt - base; if (m < 0) m = 0; if (m > K) m = K;
    if (m == 0) return;

    const float invn = 1.f / NN;
    float m0 = g_stats[lane] * invn;
    float m1 = g_stats[lane + 32] * invn;
    float v0 = g_stats[64 + lane] * invn - m0 * m0;
    float v1 = g_stats[64 + lane + 32] * invn - m1 * m1;
    float sc0 = bxw[lane] * rsqrtf(v0 + BN_EPS);
    float sc1 = bxw[lane + 32] * rsqrtf(v1 + BN_EPS);
    float sh0 = bxb[lane] - m0 * sc0;
    float sh1 = bxb[lane + 32] - m1 * sc1;

    for (int j0 = 0; j0 < m; j0 += 8) {
        int mm = m - j0; if (mm > 8) mm = 8;
        int n_[8], e_[8]; float v_[8], x0_[8], x1_[8];
        #pragma unroll
        for (int j = 0; j < 8; ++j) if (j < mm) {
            n_[j] = g_trip_n[base + j0 + j];
            e_[j] = g_trip_e[base + j0 + j];
            v_[j] = g_trip_v[base + j0 + j];
        }
        #pragma unroll
        for (int j = 0; j < 8; ++j) if (j < mm) {
            x0_[j] = g_x[(size_t)n_[j] * 64 + lane];
            x1_[j] = g_x[(size_t)n_[j] * 64 + lane + 32];
        }
        #pragma unroll
        for (int j = 0; j < 8; ++j) if (j < mm) {
            float a0 = v_[j] * fmaf(x0_[j], sc0, sh0);
            float a1 = v_[j] * fmaf(x1_[j], sc1, sh1);
            atomicAdd(&g_pm_x[(size_t)e_[j] * 64 + lane],      a0);
            atomicAdd(&g_pm_x[(size_t)e_[j] * 64 + lane + 32], a1);
        }
    }
}

// ---------------- y combine + concat/relu + BN-y stats -> out ----------------
__global__ __launch_bounds__(256) void k_y_linear(const float* __restrict__ gaw,
                                                  const float* __restrict__ gab,
                                                  const float* __restrict__ gxw,
                                                  const float* __restrict__ gxb,
                                                  const float* __restrict__ garw,
                                                  const float* __restrict__ garb,
                                                  const float* __restrict__ gxrw,
                                                  const float* __restrict__ gxrb,
                                                  float* __restrict__ out) {
    __shared__ float s_lg[16 * 64];
    __shared__ float s_pm[16 * 64];
    __shared__ float red[256], red2[256];
    int t = threadIdx.x;
    int rowbase = blockIdx.x * 16;
    reinterpret_cast<float4*>(s_lg)[t] =
        reinterpret_cast<const float4*>(g_lg_y + (size_t)rowbase * 64)[t];
    reinterpret_cast<float4*>(s_pm)[t] =
        reinterpret_cast<const float4*>(g_pm_x + (size_t)rowbase * 64)[t];
    __syncthreads();
    int c = t & 63, slot = t >> 6;
    const float *wa, *wx; float bias; bool dorelu;
    if (c < 32) { wa = gaw + c * 64;   wx = gxw + c * 64;
                  bias = gab[c] + gxb[c];            dorelu = false; }
    else        { int cr = c - 32;
                  wa = garw + cr * 64; wx = gxrw + cr * 64;
                  bias = garb[cr] + gxrb[cr];        dorelu = true;  }
    float acc[4] = {bias, bias, bias, bias};
    #pragma unroll
    for (int f = 0; f < 64; f += 4) {
        float4 wav = *reinterpret_cast<const float4*>(wa + f);
        float4 wxv = *reinterpret_cast<const float4*>(wx + f);
        #pragma unroll
        for (int j = 0; j < 4; ++j) {
            float4 pa = *reinterpret_cast<const float4*>(&s_lg[(slot + 4 * j) * 64 + f]);
            float4 px = *reinterpret_cast<const float4*>(&s_pm[(slot + 4 * j) * 64 + f]);
            float a = acc[j];
            a = fmaf(wav.x, pa.x, fmaf(wav.y, pa.y, fmaf(wav.z, pa.z, fmaf(wav.w, pa.w, a))));
            a = fmaf(wxv.x, px.x, fmaf(wxv.y, px.y, fmaf(wxv.z, px.z, fmaf(wxv.w, px.w, a))));
            acc[j] = a;
        }
    }
    float s = 0.f, sq = 0.f;
    #pragma unroll
    for (int j = 0; j < 4; ++j) {
        float v = acc[j];
        if (dorelu) v = fmaxf(v, 0.f);
        out[(size_t)(rowbase + slot + 4 * j) * 64 + c] = v;
        s += v; sq += v * v;
    }
    red[t] = s; red2[t] = sq;
    __syncthreads();
    if (slot == 0) {
        atomicAdd(&g_stats[128 + c], red[c] + red[64 + c] + red[128 + c] + red[192 + c]);
        atomicAdd(&g_stats[192 + c], red2[c] + red2[64 + c] + red2[128 + c] + red2[192 + c]);
    }
}

// ---------------- final BN on y (vectorized, in place) ----------------
__global__ __launch_bounds__(256) void k_bn_y(float4* __restrict__ buf,
                                              const float* __restrict__ w,
                                              const float* __restrict__ b) {
    int idx = blockIdx.x * 256 + threadIdx.x;
    const float inve = 1.f / EE;
    int c0 = (idx & 15) << 2;
    float4 v = buf[idx];
    float* vp = reinterpret_cast<float*>(&v);
    #pragma unroll
    for (int j = 0; j < 4; ++j) {
        int c = c0 + j;
        float m = g_stats[128 + c] * inve;
        float var = g_stats[192 + c] * inve - m * m;
        float sc = w[c] * rsqrtf(var + BN_EPS);
        vp[j] = (vp[j] - m) * sc + b[c];
    }
    buf[idx] = v;
}

// ---------------- launch: fork tail under scan B ----------------
extern "C" void kernel_launch(void* const* d_in, const int* in_sizes, int n_in,
                              void* d_out, int out_size) {
    const float* y    = (const float*)d_in[0];
    const float* lg   = (const float*)d_in[3];
    const float* pm   = (const float*)d_in[4];
    const float* pd   = (const float*)d_in[5];
    const float* tw   = (const float*)d_in[6];
    const float* tb   = (const float*)d_in[7];
    const float* trw  = (const float*)d_in[8];
    const float* trb  = (const float*)d_in[9];
    const float* gaw  = (const float*)d_in[10];
    const float* gab  = (const float*)d_in[11];
    const float* gxw  = (const float*)d_in[12];
    const float* gxb  = (const float*)d_in[13];
    const float* garw = (const float*)d_in[14];
    const float* garb = (const float*)d_in[15];
    const float* gxrw = (const float*)d_in[16];
    const float* gxrb = (const float*)d_in[17];
    const float* bxw  = (const float*)d_in[18];
    const float* bxb  = (const float*)d_in[19];
    const float* byw  = (const float*)d_in[20];
    const float* byb  = (const float*)d_in[21];
    float* out = (float*)d_out;

    static cudaStream_t s_side = nullptr;
    static cudaEvent_t ev_fork = nullptr, ev_join = nullptr;
    if (s_side == nullptr) {
        cudaStreamCreateWithFlags(&s_side, cudaStreamNonBlocking);
        cudaEventCreateWithFlags(&ev_fork, cudaEventDisableTiming);
        cudaEventCreateWithFlags(&ev_join, cudaEventDisableTiming);
    }

    k_init<<<512, 256>>>();
    // scan A: pd gather + pm triplet extract (256 MB)
    k_scan_a<<<NBLK, 256>>>(pd, pm, y);
    cudaEventRecord(ev_fork, 0);

    // side stream: x linear + pm apply, hidden under scan B
    cudaStreamWaitEvent(s_side, ev_fork, 0);
    k_x_linear<<<NN / 16, 256, 0, s_side>>>(tw, tb, trw, trb);
    k_pm_apply<<<512, 256, 0, s_side>>>(bxw, bxb);
    cudaEventRecord(ev_join, s_side);

    // main stream: scan B (lg gather, 256 MB) runs concurrently
    k_scan_b<<<NBLK, 256>>>(lg, y);
    cudaStreamWaitEvent(0, ev_join, 0);

    k_y_linear<<<EE / 16, 256>>>(gaw, gab, gxw, gxb, garw, garb, gxrw, gxrb, out);
    k_bn_y<<<512, 256>>>((float4*)out, byw, byb);
}

// round 10
// speedup vs baseline: 1.0184x; 1.0156x over previous
#include <cuda_runtime.h>
#include <cstdint>

#define NN 4096
#define EE 8192
#define FDIM 64
#define BN_EPS 1e-5f
#define TRIP_CAP 131072
#define TOTROWS (NN + EE + NN)
#define NBLK 740

// ---------------- device scratch ----------------
__device__ float g_pd_y[NN * FDIM];
__device__ float g_x[NN * FDIM];
__device__ float g_lg_y[EE * FDIM];
__device__ float g_pm_x[EE * FDIM];
__device__ float g_stats[256];
__device__ int   g_cnt;
__device__ unsigned g_row_ctr;
__device__ int   g_trip_n[TRIP_CAP];
__device__ int   g_trip_e[TRIP_CAP];
__device__ float g_trip_v[TRIP_CAP];

// ---------------- init ----------------
__global__ __launch_bounds__(256) void k_init() {
    int idx = blockIdx.x * 256 + threadIdx.x;              // 512*256 = 131072
    reinterpret_cast<float4*>(g_pm_x)[idx] = make_float4(0.f, 0.f, 0.f, 0.f);
    if (idx < 256) g_stats[idx] = 0.f;
    if (idx == 0) { g_cnt = 0; g_row_ctr = 0u; }
}

// ---------------- helpers ----------------
__device__ __forceinline__ unsigned nz4(float4 v) {
    return __float_as_uint(v.x) | __float_as_uint(v.y) |
           __float_as_uint(v.z) | __float_as_uint(v.w);
}

__device__ __forceinline__ void gath_chunk(float4 v, unsigned ored, int colbase, int lane,
                                           const float* __restrict__ B,
                                           float& acc0, float& acc1) {
    unsigned mask = __ballot_sync(0xffffffffu, ored != 0u);
    while (mask) {
        int src = __ffs(mask) - 1;
        mask &= mask - 1;
        float b0 = __shfl_sync(0xffffffffu, v.x, src);
        float b1 = __shfl_sync(0xffffffffu, v.y, src);
        float b2 = __shfl_sync(0xffffffffu, v.z, src);
        float b3 = __shfl_sync(0xffffffffu, v.w, src);
        const float* bp = B + (size_t)(colbase + (src << 2)) * FDIM + lane;
        if (b0 != 0.f) { acc0 = fmaf(b0, bp[0],   acc0); acc1 = fmaf(b0, bp[32],  acc1); }
        if (b1 != 0.f) { acc0 = fmaf(b1, bp[64],  acc0); acc1 = fmaf(b1, bp[96],  acc1); }
        if (b2 != 0.f) { acc0 = fmaf(b2, bp[128], acc0); acc1 = fmaf(b2, bp[160], acc1); }
        if (b3 != 0.f) { acc0 = fmaf(b3, bp[192], acc0); acc1 = fmaf(b3, bp[224], acc1); }
    }
}

__device__ __forceinline__ void pm_emit(float4 v, int col0, int n) {
    int k = (v.x != 0.f) + (v.y != 0.f) + (v.z != 0.f) + (v.w != 0.f);
    if (!k) return;
    int pos = atomicAdd(&g_cnt, k);
    float vals[4] = {v.x, v.y, v.z, v.w};
    #pragma unroll
    for (int j = 0; j < 4; ++j) {
        if (vals[j] != 0.f && pos < TRIP_CAP) {
            g_trip_n[pos] = n;
            g_trip_e[pos] = col0 + j;
            g_trip_v[pos] = vals[j];
            ++pos;
        }
    }
}

__device__ __forceinline__ void red_v4(float* ptr, float4 a) {
    asm volatile("red.global.add.v4.f32 [%0], {%1, %2, %3, %4};"
                 :: "l"(ptr), "f"(a.x), "f"(a.y), "f"(a.z), "f"(a.w)
                 : "memory");
}

// ---------------- persistent mega-scan (R4/R7, proven) ----------------
__global__ void __launch_bounds__(256, 5) k_megascan(const float* __restrict__ pd,
                                                     const float* __restrict__ lg,
                                                     const float* __restrict__ pm,
                                                     const float* __restrict__ y) {
    int lane = threadIdx.x & 31;
    while (true) {
        unsigned rowid;
        if (lane == 0) rowid = atomicAdd(&g_row_ctr, 1u);
        rowid = __shfl_sync(0xffffffffu, rowid, 0);
        if (rowid >= TOTROWS) return;

        const float4* arow;
        int mode, row;
        if (rowid < NN)            { mode = 0; row = (int)rowid;           arow = reinterpret_cast<const float4*>(pd + (size_t)row * EE); }
        else if (rowid < NN + EE)  { mode = 1; row = (int)rowid - NN;      arow = reinterpret_cast<const float4*>(lg + (size_t)row * EE); }
        else                       { mode = 2; row = (int)rowid - NN - EE; arow = reinterpret_cast<const float4*>(pm + (size_t)row * EE); }

        if (mode < 2) {
            float acc0 = 0.f, acc1 = 0.f;
            #pragma unroll 1
            for (int g = 0; g < EE / 512; ++g) {
                int fb = (g << 7) + lane;
                float4 v0 = __ldcs(arow + fb);
                float4 v1 = __ldcs(arow + fb + 32);
                float4 v2 = __ldcs(arow + fb + 64);
                float4 v3 = __ldcs(arow + fb + 96);
                unsigned o0 = nz4(v0), o1 = nz4(v1), o2 = nz4(v2), o3 = nz4(v3);
                if (__ballot_sync(0xffffffffu, (o0 | o1 | o2 | o3) != 0u)) {
                    int cb = g << 9;
                    gath_chunk(v0, o0, cb,       lane, y, acc0, acc1);
                    gath_chunk(v1, o1, cb + 128, lane, y, acc0, acc1);
                    gath_chunk(v2, o2, cb + 256, lane, y, acc0, acc1);
                    gath_chunk(v3, o3, cb + 384, lane, y, acc0, acc1);
                }
            }
            float* out = (mode == 0 ? g_pd_y : g_lg_y) + (size_t)row * FDIM;
            out[lane]      = acc0;
            out[lane + 32] = acc1;
        } else {
            #pragma unroll 1
            for (int g = 0; g < EE / 512; ++g) {
                int fb = (g << 7) + lane;
                float4 v0 = __ldcs(arow + fb);
                float4 v1 = __ldcs(arow + fb + 32);
                float4 v2 = __ldcs(arow + fb + 64);
                float4 v3 = __ldcs(arow + fb + 96);
                unsigned o0 = nz4(v0), o1 = nz4(v1), o2 = nz4(v2), o3 = nz4(v3);
                if (__ballot_sync(0xffffffffu, (o0 | o1 | o2 | o3) != 0u)) {
                    int cb = (g << 9) + (lane << 2);
                    if (o0) pm_emit(v0, cb,       row);
                    if (o1) pm_emit(v1, cb + 128, row);
                    if (o2) pm_emit(v2, cb + 256, row);
                    if (o3) pm_emit(v3, cb + 384, row);
                }
            }
        }
    }
}

// ---------------- x linear + concat/relu + BN-x stats ----------------
__global__ __launch_bounds__(256) void k_x_linear(const float* __restrict__ tw,
                                                  const float* __restrict__ tb,
                                                  const float* __restrict__ trw,
                                                  const float* __restrict__ trb) {
    __shared__ float s_in[16 * 64];
    __shared__ float red[256], red2[256];
    int t = threadIdx.x;
    int rowbase = blockIdx.x * 16;
    reinterpret_cast<float4*>(s_in)[t] =
        reinterpret_cast<const float4*>(g_pd_y + (size_t)rowbase * 64)[t];
    __syncthreads();
    int c = t & 63, slot = t >> 6;
    const float* w; float bias; bool dorelu;
    if (c < 32) { w = tw + c * 64;         bias = tb[c];        dorelu = false; }
    else        { w = trw + (c - 32) * 64; bias = trb[c - 32];  dorelu = true;  }
    float acc[4] = {bias, bias, bias, bias};
    #pragma unroll
    for (int f = 0; f < 64; f += 4) {
        float4 wv = *reinterpret_cast<const float4*>(w + f);
        #pragma unroll
        for (int j = 0; j < 4; ++j) {
            float4 pv = *reinterpret_cast<const float4*>(&s_in[(slot + 4 * j) * 64 + f]);
            acc[j] = fmaf(wv.x, pv.x, fmaf(wv.y, pv.y, fmaf(wv.z, pv.z, fmaf(wv.w, pv.w, acc[j]))));
        }
    }
    float s = 0.f, sq = 0.f;
    #pragma unroll
    for (int j = 0; j < 4; ++j) {
        float v = acc[j];
        if (dorelu) v = fmaxf(v, 0.f);
        g_x[(size_t)(rowbase + slot + 4 * j) * 64 + c] = v;
        s += v; sq += v * v;
    }
    red[t] = s; red2[t] = sq;
    __syncthreads();
    if (slot == 0) {
        atomicAdd(&g_stats[c],      red[c] + red[64 + c] + red[128 + c] + red[192 + c]);
        atomicAdd(&g_stats[64 + c], red2[c] + red2[64 + c] + red2[128 + c] + red2[192 + c]);
    }
}

// ---------------- pm triplet apply, fused x-BN, v4 reductions ----------------
// Each half-warp handles one triplet: 16 lanes x red.v4 covers 64 floats.
__global__ __launch_bounds__(256) void k_pm_apply(const float* __restrict__ bxw,
                                                  const float* __restrict__ bxb) {
    int lane = threadIdx.x & 31;
    int warp = (blockIdx.x * 256 + threadIdx.x) >> 5;   // 4096 warps
    int half = lane >> 4;                                // 0/1: triplet within pair
    int q = lane & 15;                                   // cols [4q, 4q+4)

    int cnt = g_cnt;
    if (cnt > TRIP_CAP) cnt = TRIP_CAP;
    int npairs = (cnt + 1) >> 1;

    // BN-x affine for this lane's 4 channels
    const float invn = 1.f / NN;
    float4 s4 = *reinterpret_cast<const float4*>(&g_stats[q * 4]);
    float4 q4 = *reinterpret_cast<const float4*>(&g_stats[64 + q * 4]);
    float4 w4 = *reinterpret_cast<const float4*>(&bxw[q * 4]);
    float4 b4 = *reinterpret_cast<const float4*>(&bxb[q * 4]);
    float sc[4], sh[4];
    {
        float mm, vv;
        mm = s4.x * invn; vv = q4.x * invn - mm * mm; sc[0] = w4.x * rsqrtf(vv + BN_EPS); sh[0] = b4.x - mm * sc[0];
        mm = s4.y * invn; vv = q4.y * invn - mm * mm; sc[1] = w4.y * rsqrtf(vv + BN_EPS); sh[1] = b4.y - mm * sc[1];
        mm = s4.z * invn; vv = q4.z * invn - mm * mm; sc[2] = w4.z * rsqrtf(vv + BN_EPS); sh[2] = b4.z - mm * sc[2];
        mm = s4.w * invn; vv = q4.w * invn - mm * mm; sc[3] = w4.w * rsqrtf(vv + BN_EPS); sh[3] = b4.w - mm * sc[3];
    }

    for (int p = warp; p < npairs; p += 4096) {
        int i = p * 2 + half;
        if (i < cnt) {
            int n = g_trip_n[i];
            int e = g_trip_e[i];
            float val = g_trip_v[i];
            float4 xv = *reinterpret_cast<const float4*>(&g_x[(size_t)n * 64 + q * 4]);
            float4 a;
            a.x = val * fmaf(xv.x, sc[0], sh[0]);
            a.y = val * fmaf(xv.y, sc[1], sh[1]);
            a.z = val * fmaf(xv.z, sc[2], sh[2]);
            a.w = val * fmaf(xv.w, sc[3], sh[3]);
            red_v4(&g_pm_x[(size_t)e * 64 + q * 4], a);
        }
    }
}

// ---------------- y combine + concat/relu + BN-y stats -> out ----------------
__global__ __launch_bounds__(256) void k_y_linear(const float* __restrict__ gaw,
                                                  const float* __restrict__ gab,
                                                  const float* __restrict__ gxw,
                                                  const float* __restrict__ gxb,
                                                  const float* __restrict__ garw,
                                                  const float* __restrict__ garb,
                                                  const float* __restrict__ gxrw,
                                                  const float* __restrict__ gxrb,
                                                  float* __restrict__ out) {
    __shared__ float s_lg[16 * 64];
    __shared__ float s_pm[16 * 64];
    __shared__ float red[256], red2[256];
    int t = threadIdx.x;
    int rowbase = blockIdx.x * 16;
    reinterpret_cast<float4*>(s_lg)[t] =
        reinterpret_cast<const float4*>(g_lg_y + (size_t)rowbase * 64)[t];
    reinterpret_cast<float4*>(s_pm)[t] =
        reinterpret_cast<const float4*>(g_pm_x + (size_t)rowbase * 64)[t];
    __syncthreads();
    int c = t & 63, slot = t >> 6;
    const float *wa, *wx; float bias; bool dorelu;
    if (c < 32) { wa = gaw + c * 64;   wx = gxw + c * 64;
                  bias = gab[c] + gxb[c];            dorelu = false; }
    else        { int cr = c - 32;
                  wa = garw + cr * 64; wx = gxrw + cr * 64;
                  bias = garb[cr] + gxrb[cr];        dorelu = true;  }
    float acc[4] = {bias, bias, bias, bias};
    #pragma unroll
    for (int f = 0; f < 64; f += 4) {
        float4 wav = *reinterpret_cast<const float4*>(wa + f);
        float4 wxv = *reinterpret_cast<const float4*>(wx + f);
        #pragma unroll
        for (int j = 0; j < 4; ++j) {
            float4 pa = *reinterpret_cast<const float4*>(&s_lg[(slot + 4 * j) * 64 + f]);
            float4 px = *reinterpret_cast<const float4*>(&s_pm[(slot + 4 * j) * 64 + f]);
            float a = acc[j];
            a = fmaf(wav.x, pa.x, fmaf(wav.y, pa.y, fmaf(wav.z, pa.z, fmaf(wav.w, pa.w, a))));
            a = fmaf(wxv.x, px.x, fmaf(wxv.y, px.y, fmaf(wxv.z, px.z, fmaf(wxv.w, px.w, a))));
            acc[j] = a;
        }
    }
    float s = 0.f, sq = 0.f;
    #pragma unroll
    for (int j = 0; j < 4; ++j) {
        float v = acc[j];
        if (dorelu) v = fmaxf(v, 0.f);
        out[(size_t)(rowbase + slot + 4 * j) * 64 + c] = v;
        s += v; sq += v * v;
    }
    red[t] = s; red2[t] = sq;
    __syncthreads();
    if (slot == 0) {
        atomicAdd(&g_stats[128 + c], red[c] + red[64 + c] + red[128 + c] + red[192 + c]);
        atomicAdd(&g_stats[192 + c], red2[c] + red2[64 + c] + red2[128 + c] + red2[192 + c]);
    }
}

// ---------------- final BN on y (vectorized, in place) ----------------
__global__ __launch_bounds__(256) void k_bn_y(float4* __restrict__ buf,
                                              const float* __restrict__ w,
                                              const float* __restrict__ b) {
    int idx = blockIdx.x * 256 + threadIdx.x;
    const float inve = 1.f / EE;
    int c0 = (idx & 15) << 2;
    float4 v = buf[idx];
    float* vp = reinterpret_cast<float*>(&v);
    #pragma unroll
    for (int j = 0; j < 4; ++j) {
        int c = c0 + j;
        float m = g_stats[128 + c] * inve;
        float var = g_stats[192 + c] * inve - m * m;
        float sc = w[c] * rsqrtf(var + BN_EPS);
        vp[j] = (vp[j] - m) * sc + b[c];
    }
    buf[idx] = v;
}

// ---------------- launch ----------------
extern "C" void kernel_launch(void* const* d_in, const int* in_sizes, int n_in,
                              void* d_out, int out_size) {
    const float* y    = (const float*)d_in[0];
    const float* lg   = (const float*)d_in[3];
    const float* pm   = (const float*)d_in[4];
    const float* pd   = (const float*)d_in[5];
    const float* tw   = (const float*)d_in[6];
    const float* tb   = (const float*)d_in[7];
    const float* trw  = (const float*)d_in[8];
    const float* trb  = (const float*)d_in[9];
    const float* gaw  = (const float*)d_in[10];
    const float* gab  = (const float*)d_in[11];
    const float* gxw  = (const float*)d_in[12];
    const float* gxb  = (const float*)d_in[13];
    const float* garw = (const float*)d_in[14];
    const float* garb = (const float*)d_in[15];
    const float* gxrw = (const float*)d_in[16];
    const float* gxrb = (const float*)d_in[17];
    const float* bxw  = (const float*)d_in[18];
    const float* bxb  = (const float*)d_in[19];
    const float* byw  = (const float*)d_in[20];
    const float* byb  = (const float*)d_in[21];
    float* out = (float*)d_out;

    k_init<<<512, 256>>>();
    k_megascan<<<NBLK, 256>>>(pd, lg, pm, y);
    k_x_linear<<<NN / 16, 256>>>(tw, tb, trw, trb);
    k_pm_apply<<<512, 256>>>(bxw, bxb);
    k_y_linear<<<EE / 16, 256>>>(gaw, gab, gxw, gxb, garw, garb, gxrw, gxrb, out);
    k_bn_y<<<512, 256>>>((float4*)out, byw, byb);
}

// round 11
// speedup vs baseline: 1.0493x; 1.0304x over previous
#include <cuda_runtime.h>
#include <cstdint>

#define NN 4096
#define EE 8192
#define FDIM 64
#define BN_EPS 1e-5f
#define BKT 16
#define TOTROWS (NN + EE + NN)
#define NBLK 740

// ---------------- device scratch ----------------
__device__ float g_pd_y[NN * FDIM];
__device__ float g_x[NN * FDIM];        // raw x (pre-BN)
__device__ float g_lg_y[EE * FDIM];
__device__ float g_stats[256];
__device__ unsigned g_row_ctr;
__device__ int   g_bkt_cnt[EE];
__device__ int   g_bkt_n[EE * BKT];
__device__ float g_bkt_v[EE * BKT];

// ---------------- init: stats + bucket counters + row counter ----------------
__global__ __launch_bounds__(256) void k_init() {
    int idx = blockIdx.x * 256 + threadIdx.x;    // 32*256 = 8192
    g_bkt_cnt[idx] = 0;
    if (idx < 256) g_stats[idx] = 0.f;
    if (idx == 0) g_row_ctr = 0u;
}

// ---------------- helpers ----------------
__device__ __forceinline__ unsigned nz4(float4 v) {
    return __float_as_uint(v.x) | __float_as_uint(v.y) |
           __float_as_uint(v.z) | __float_as_uint(v.w);
}

__device__ __forceinline__ void gath_chunk(float4 v, unsigned ored, int colbase, int lane,
                                           const float* __restrict__ B,
                                           float& acc0, float& acc1) {
    unsigned mask = __ballot_sync(0xffffffffu, ored != 0u);
    while (mask) {
        int src = __ffs(mask) - 1;
        mask &= mask - 1;
        float b0 = __shfl_sync(0xffffffffu, v.x, src);
        float b1 = __shfl_sync(0xffffffffu, v.y, src);
        float b2 = __shfl_sync(0xffffffffu, v.z, src);
        float b3 = __shfl_sync(0xffffffffu, v.w, src);
        const float* bp = B + (size_t)(colbase + (src << 2)) * FDIM + lane;
        if (b0 != 0.f) { acc0 = fmaf(b0, bp[0],   acc0); acc1 = fmaf(b0, bp[32],  acc1); }
        if (b1 != 0.f) { acc0 = fmaf(b1, bp[64],  acc0); acc1 = fmaf(b1, bp[96],  acc1); }
        if (b2 != 0.f) { acc0 = fmaf(b2, bp[128], acc0); acc1 = fmaf(b2, bp[160], acc1); }
        if (b3 != 0.f) { acc0 = fmaf(b3, bp[192], acc0); acc1 = fmaf(b3, bp[224], acc1); }
    }
}

// emit pm nonzeros into per-edge buckets
__device__ __forceinline__ void pm_emit(float4 v, int col0, int n) {
    float vals[4] = {v.x, v.y, v.z, v.w};
    #pragma unroll
    for (int j = 0; j < 4; ++j) {
        if (vals[j] != 0.f) {
            int e = col0 + j;
            int slot = atomicAdd(&g_bkt_cnt[e], 1);
            if (slot < BKT) {
                g_bkt_n[e * BKT + slot] = n;
                g_bkt_v[e * BKT + slot] = vals[j];
            }
        }
    }
}

// ---------------- persistent mega-scan (proven) ----------------
// rows: pd [0,4096), lg [4096,12288), pm [12288,16384)
__global__ void __launch_bounds__(256, 5) k_megascan(const float* __restrict__ pd,
                                                     const float* __restrict__ lg,
                                                     const float* __restrict__ pm,
                                                     const float* __restrict__ y) {
    int lane = threadIdx.x & 31;
    while (true) {
        unsigned rowid;
        if (lane == 0) rowid = atomicAdd(&g_row_ctr, 1u);
        rowid = __shfl_sync(0xffffffffu, rowid, 0);
        if (rowid >= TOTROWS) return;

        const float4* arow;
        int mode, row;
        if (rowid < NN)            { mode = 0; row = (int)rowid;           arow = reinterpret_cast<const float4*>(pd + (size_t)row * EE); }
        else if (rowid < NN + EE)  { mode = 1; row = (int)rowid - NN;      arow = reinterpret_cast<const float4*>(lg + (size_t)row * EE); }
        else                       { mode = 2; row = (int)rowid - NN - EE; arow = reinterpret_cast<const float4*>(pm + (size_t)row * EE); }

        if (mode < 2) {
            float acc0 = 0.f, acc1 = 0.f;
            #pragma unroll 1
            for (int g = 0; g < EE / 512; ++g) {
                int fb = (g << 7) + lane;
                float4 v0 = __ldcs(arow + fb);
                float4 v1 = __ldcs(arow + fb + 32);
                float4 v2 = __ldcs(arow + fb + 64);
                float4 v3 = __ldcs(arow + fb + 96);
                unsigned o0 = nz4(v0), o1 = nz4(v1), o2 = nz4(v2), o3 = nz4(v3);
                if (__ballot_sync(0xffffffffu, (o0 | o1 | o2 | o3) != 0u)) {
                    int cb = g << 9;
                    gath_chunk(v0, o0, cb,       lane, y, acc0, acc1);
                    gath_chunk(v1, o1, cb + 128, lane, y, acc0, acc1);
                    gath_chunk(v2, o2, cb + 256, lane, y, acc0, acc1);
                    gath_chunk(v3, o3, cb + 384, lane, y, acc0, acc1);
                }
            }
            float* out = (mode == 0 ? g_pd_y : g_lg_y) + (size_t)row * FDIM;
            out[lane]      = acc0;
            out[lane + 32] = acc1;
        } else {
            #pragma unroll 1
            for (int g = 0; g < EE / 512; ++g) {
                int fb = (g << 7) + lane;
                float4 v0 = __ldcs(arow + fb);
                float4 v1 = __ldcs(arow + fb + 32);
                float4 v2 = __ldcs(arow + fb + 64);
                float4 v3 = __ldcs(arow + fb + 96);
                unsigned o0 = nz4(v0), o1 = nz4(v1), o2 = nz4(v2), o3 = nz4(v3);
                if (__ballot_sync(0xffffffffu, (o0 | o1 | o2 | o3) != 0u)) {
                    int cb = (g << 9) + (lane << 2);
                    if (o0) pm_emit(v0, cb,       row);
                    if (o1) pm_emit(v1, cb + 128, row);
                    if (o2) pm_emit(v2, cb + 256, row);
                    if (o3) pm_emit(v3, cb + 384, row);
                }
            }
        }
    }
}

// ---------------- x linear + concat/relu + BN-x stats ----------------
__global__ __launch_bounds__(256) void k_x_linear(const float* __restrict__ tw,
                                                  const float* __restrict__ tb,
                                                  const float* __restrict__ trw,
                                                  const float* __restrict__ trb) {
    __shared__ float s_in[16 * 64];
    __shared__ float red[256], red2[256];
    int t = threadIdx.x;
    int rowbase = blockIdx.x * 16;
    reinterpret_cast<float4*>(s_in)[t] =
        reinterpret_cast<const float4*>(g_pd_y + (size_t)rowbase * 64)[t];
    __syncthreads();
    int c = t & 63, slot = t >> 6;
    const float* w; float bias; bool dorelu;
    if (c < 32) { w = tw + c * 64;         bias = tb[c];        dorelu = false; }
    else        { w = trw + (c - 32) * 64; bias = trb[c - 32];  dorelu = true;  }
    float acc[4] = {bias, bias, bias, bias};
    #pragma unroll
    for (int f = 0; f < 64; f += 4) {
        float4 wv = *reinterpret_cast<const float4*>(w + f);
        #pragma unroll
        for (int j = 0; j < 4; ++j) {
            float4 pv = *reinterpret_cast<const float4*>(&s_in[(slot + 4 * j) * 64 + f]);
            acc[j] = fmaf(wv.x, pv.x, fmaf(wv.y, pv.y, fmaf(wv.z, pv.z, fmaf(wv.w, pv.w, acc[j]))));
        }
    }
    float s = 0.f, sq = 0.f;
    #pragma unroll
    for (int j = 0; j < 4; ++j) {
        float v = acc[j];
        if (dorelu) v = fmaxf(v, 0.f);
        g_x[(size_t)(rowbase + slot + 4 * j) * 64 + c] = v;
        s += v; sq += v * v;
    }
    red[t] = s; red2[t] = sq;
    __syncthreads();
    if (slot == 0) {
        atomicAdd(&g_stats[c],      red[c] + red[64 + c] + red[128 + c] + red[192 + c]);
        atomicAdd(&g_stats[64 + c], red2[c] + red2[64 + c] + red2[128 + c] + red2[192 + c]);
    }
}

// ---------------- y: inline pm gather (BN-x fused) + combine + relu + BN-y stats -> out ----------------
__global__ __launch_bounds__(256) void k_y_linear(const float* __restrict__ gaw,
                                                  const float* __restrict__ gab,
                                                  const float* __restrict__ gxw,
                                                  const float* __restrict__ gxb,
                                                  const float* __restrict__ garw,
                                                  const float* __restrict__ garb,
                                                  const float* __restrict__ gxrw,
                                                  const float* __restrict__ gxrb,
                                                  const float* __restrict__ bxw,
                                                  const float* __restrict__ bxb,
                                                  float* __restrict__ out) {
    __shared__ float s_lg[16 * 64];
    __shared__ float s_pm[16 * 64];
    __shared__ float s_sc[64], s_sh[64];
    __shared__ float red[256], red2[256];
    int t = threadIdx.x;
    int lane = t & 31;
    int w = t >> 5;
    int rowbase = blockIdx.x * 16;

    // BN-x affine (stats final: x_linear kernel completed before this launch)
    if (t < 64) {
        const float invn = 1.f / NN;
        float m = g_stats[t] * invn;
        float var = g_stats[64 + t] * invn - m * m;
        float sc = bxw[t] * rsqrtf(var + BN_EPS);
        s_sc[t] = sc;
        s_sh[t] = bxb[t] - m * sc;
    }
    reinterpret_cast<float4*>(s_lg)[t] =
        reinterpret_cast<const float4*>(g_lg_y + (size_t)rowbase * 64)[t];
    __syncthreads();

    // pm gather: warp w handles edges rowbase+2w, rowbase+2w+1
    {
        float scl0 = s_sc[lane],      shl0 = s_sh[lane];
        float scl1 = s_sc[lane + 32], shl1 = s_sh[lane + 32];
        #pragma unroll
        for (int h = 0; h < 2; ++h) {
            int eslot = 2 * w + h;
            int e = rowbase + eslot;
            int cnt = g_bkt_cnt[e];
            if (cnt > BKT) cnt = BKT;
            float a0 = 0.f, a1 = 0.f;
            for (int j = 0; j < cnt; ++j) {
                int n = g_bkt_n[e * BKT + j];          // broadcast
                float val = g_bkt_v[e * BKT + j];
                float xv0 = g_x[(size_t)n * 64 + lane];
                float xv1 = g_x[(size_t)n * 64 + lane + 32];
                a0 = fmaf(val, fmaf(xv0, scl0, shl0), a0);
                a1 = fmaf(val, fmaf(xv1, scl1, shl1), a1);
            }
            s_pm[eslot * 64 + lane]      = a0;
            s_pm[eslot * 64 + lane + 32] = a1;
        }
    }
    __syncthreads();

    int c = t & 63, slot = t >> 6;
    const float *wa, *wx; float bias; bool dorelu;
    if (c < 32) { wa = gaw + c * 64;   wx = gxw + c * 64;
                  bias = gab[c] + gxb[c];            dorelu = false; }
    else        { int cr = c - 32;
                  wa = garw + cr * 64; wx = gxrw + cr * 64;
                  bias = garb[cr] + gxrb[cr];        dorelu = true;  }
    float acc[4] = {bias, bias, bias, bias};
    #pragma unroll
    for (int f = 0; f < 64; f += 4) {
        float4 wav = *reinterpret_cast<const float4*>(wa + f);
        float4 wxv = *reinterpret_cast<const float4*>(wx + f);
        #pragma unroll
        for (int j = 0; j < 4; ++j) {
            float4 pa = *reinterpret_cast<const float4*>(&s_lg[(slot + 4 * j) * 64 + f]);
            float4 px = *reinterpret_cast<const float4*>(&s_pm[(slot + 4 * j) * 64 + f]);
            float a = acc[j];
            a = fmaf(wav.x, pa.x, fmaf(wav.y, pa.y, fmaf(wav.z, pa.z, fmaf(wav.w, pa.w, a))));
            a = fmaf(wxv.x, px.x, fmaf(wxv.y, px.y, fmaf(wxv.z, px.z, fmaf(wxv.w, px.w, a))));
            acc[j] = a;
        }
    }
    float s = 0.f, sq = 0.f;
    #pragma unroll
    for (int j = 0; j < 4; ++j) {
        float v = acc[j];
        if (dorelu) v = fmaxf(v, 0.f);
        out[(size_t)(rowbase + slot + 4 * j) * 64 + c] = v;
        s += v; sq += v * v;
    }
    red[t] = s; red2[t] = sq;
    __syncthreads();
    if (slot == 0) {
        atomicAdd(&g_stats[128 + c], red[c] + red[64 + c] + red[128 + c] + red[192 + c]);
        atomicAdd(&g_stats[192 + c], red2[c] + red2[64 + c] + red2[128 + c] + red2[192 + c]);
    }
}

// ---------------- final BN on y (vectorized, in place) ----------------
__global__ __launch_bounds__(256) void k_bn_y(float4* __restrict__ buf,
                                              const float* __restrict__ w,
                                              const float* __restrict__ b) {
    int idx = blockIdx.x * 256 + threadIdx.x;
    const float inve = 1.f / EE;
    int c0 = (idx & 15) << 2;
    float4 v = buf[idx];
    float* vp = reinterpret_cast<float*>(&v);
    #pragma unroll
    for (int j = 0; j < 4; ++j) {
        int c = c0 + j;
        float m = g_stats[128 + c] * inve;
        float var = g_stats[192 + c] * inve - m * m;
        float sc = w[c] * rsqrtf(var + BN_EPS);
        vp[j] = (vp[j] - m) * sc + b[c];
    }
    buf[idx] = v;
}

// ---------------- launch ----------------
extern "C" void kernel_launch(void* const* d_in, const int* in_sizes, int n_in,
                              void* d_out, int out_size) {
    const float* y    = (const float*)d_in[0];
    const float* lg   = (const float*)d_in[3];
    const float* pm   = (const float*)d_in[4];
    const float* pd   = (const float*)d_in[5];
    const float* tw   = (const float*)d_in[6];
    const float* tb   = (const float*)d_in[7];
    const float* trw  = (const float*)d_in[8];
    const float* trb  = (const float*)d_in[9];
    const float* gaw  = (const float*)d_in[10];
    const float* gab  = (const float*)d_in[11];
    const float* gxw  = (const float*)d_in[12];
    const float* gxb  = (const float*)d_in[13];
    const float* garw = (const float*)d_in[14];
    const float* garb = (const float*)d_in[15];
    const float* gxrw = (const float*)d_in[16];
    const float* gxrb = (const float*)d_in[17];
    const float* bxw  = (const float*)d_in[18];
    const float* bxb  = (const float*)d_in[19];
    const float* byw  = (const float*)d_in[20];
    const float* byb  = (const float*)d_in[21];
    float* out = (float*)d_out;

    k_init<<<32, 256>>>();
    k_megascan<<<NBLK, 256>>>(pd, lg, pm, y);
    k_x_linear<<<NN / 16, 256>>>(tw, tb, trw, trb);
    k_y_linear<<<EE / 16, 256>>>(gaw, gab, gxw, gxb, garw, garb, gxrw, gxrb,
                                 bxw, bxb, out);
    k_bn_y<<<512, 256>>>((float4*)out, byw, byb);
}